// round 14
// baseline (speedup 1.0000x reference)
#include <cuda_runtime.h>
#include <cuda_fp16.h>
#include <cstdint>

// Shapes
#define NB   8
#define NTOK 8192      // N * I * J
#define XD   256
#define RD   256
#define UD   64
#define VD   64
#define HD   128

// Scratch (allocation-free: __device__ globals)
__device__ __half   g_th[NB * HD * RD];      // t[n,h,r] fp16 TRANSPOSED (r contiguous)
__device__ __half   g_vh[NTOK * HD];         // v[tok,h] fp16
__device__ __half   g_w2h[XD * VD * HD];     // fragment-packed fp16 w2 * 1024 (4MB)
__device__ float    g_part[2][NTOK * VD];    // K-split partials (scaled by 1024)
__device__ unsigned g_cnt[64];               // per-tile arrival counters (self-resetting)

#define PACKS_H2(d, lo, hi) /* d = fp16x2 {lo,hi} * 1024 */                    \
    asm("cvt.rn.f16x2.f32 %0, %1, %2;" : "=r"(d) : "f"((hi) * 1024.0f), "f"((lo) * 1024.0f))
#define PACK_H2(d, lo, hi)  /* d = fp16x2 {lo,hi} */                           \
    asm("cvt.rn.f16x2.f32 %0, %1, %2;" : "=r"(d) : "f"(hi), "f"(lo))
#define HMUL2(d, a, b) \
    asm("mul.rn.f16x2 %0, %1, %2;" : "=r"(d) : "r"(a), "r"(b))
#define SPLAT16(d, hp) /* duplicate one fp16 into both halves */               \
    asm("mov.b32 %0, {%1, %1};" : "=r"(d) : "h"(hp))
#define MMA_F16(ac, a0, a1, a2, a3, b0, b1)                                    \
    asm volatile("mma.sync.aligned.m16n8k16.row.col.f32.f16.f16.f32 "          \
        "{%0,%1,%2,%3}, {%4,%5,%6,%7}, {%8,%9}, {%0,%1,%2,%3};"                \
        : "+f"((ac)[0]), "+f"((ac)[1]), "+f"((ac)[2]), "+f"((ac)[3])           \
        : "r"(a0), "r"(a1), "r"(a2), "r"(a3), "r"(b0), "r"(b1))

extern __shared__ __align__(128) char g_smem_raw[];

// ---------------------------------------------------------------------------
// Kernel W: fragment-pack w2 for kC (fp16, scaled by 2^10 exact).
// vv-major layout: byte = x0*16384 + vv*256 + hcp*64 + kl*16 + slot*2
// so a vv-quarter's per-x0 slice (16 vv x 256B = 4KB) is contiguous.
// slot = codd*4 + breg*2 + dlt; h = hcp*32 + codd*16 + breg*8 + kl*2 + dlt.
// One thread -> one coalesced STG.128 of 8 halves. GRID MUST BE 1024 (x0<256).
// ---------------------------------------------------------------------------
__global__ void kW(const float* __restrict__ w2) {
    int gid = blockIdx.x * 256 + threadIdx.x;     // 0 .. 262143
    int kl  = gid & 3;
    int hcp = (gid >> 2) & 3;
    int vv  = (gid >> 4) & 63;
    int x0  = gid >> 10;

    const float* src = w2 + (size_t)x0 * (VD * HD) + (size_t)vv * HD;
    uint4 o;
    {
        int hb = hcp * 32 + kl * 2;
        float2 a = *reinterpret_cast<const float2*>(src + hb);
        float2 b = *reinterpret_cast<const float2*>(src + hb + 8);
        float2 c = *reinterpret_cast<const float2*>(src + hb + 16);
        float2 d = *reinterpret_cast<const float2*>(src + hb + 24);
        PACKS_H2(o.x, a.x, a.y);
        PACKS_H2(o.y, b.x, b.y);
        PACKS_H2(o.z, c.x, c.y);
        PACKS_H2(o.w, d.x, d.y);
    }
    char* dst = reinterpret_cast<char*>(g_w2h)
              + (size_t)x0 * 16384 + vv * 256 + hcp * 64 + kl * 16;
    *reinterpret_cast<uint4*>(dst) = o;
}

// ---------------------------------------------------------------------------
// Kernel A: t[n,r,h] = sum_u ( sum_v u[n,r,u,v] ) * w1[r,u,h]
// 256 blocks (one per r) looping the 8 n's; writes fp16 transposed g_th[n][h][r].
// ---------------------------------------------------------------------------
#define UAS 68
__global__ void kA(const float* __restrict__ u, const float* __restrict__ w1) {
    const int rr  = blockIdx.x;
    const int tid = threadIdx.x;            // 0..255

    __shared__ float us[UD * UAS];
    __shared__ float s[2][UD];

    const float* w1b = w1 + (size_t)rr * UD * HD + (tid & 127);

    for (int n = 0; n < NB; n++) {
        const float4* ub4 = reinterpret_cast<const float4*>(
            u + (size_t)(n * RD + rr) * (UD * VD));
        #pragma unroll
        for (int j = 0; j < 4; j++) {
            int idx = tid + j * 256;        // 0..1023 float4
            int row = idx >> 4, col = idx & 15;
            *reinterpret_cast<float4*>(&us[row * UAS + col * 4]) = ub4[idx];
        }
        __syncthreads();

        {   // Phase 1: sum over v (64) -> s[n&1][u]
            int uu = tid >> 2, part = tid & 3;
            const float4* p4 = reinterpret_cast<const float4*>(&us[uu * UAS + part * 16]);
            float4 a = p4[0], b = p4[1], c = p4[2], d = p4[3];
            float sum = ((a.x + a.y) + (a.z + a.w)) + ((b.x + b.y) + (b.z + b.w))
                      + ((c.x + c.y) + (c.z + c.w)) + ((d.x + d.y) + (d.z + d.w));
            sum += __shfl_xor_sync(0xffffffffu, sum, 1);
            sum += __shfl_xor_sync(0xffffffffu, sum, 2);
            if (part == 0) s[n & 1][uu] = sum;
        }
        __syncthreads();

        if (tid < HD) {
            const float* ss = s[n & 1];
            float a0 = 0.f, a1 = 0.f, a2 = 0.f, a3 = 0.f;
            #pragma unroll 4
            for (int uu = 0; uu < UD; uu += 4) {
                a0 += ss[uu + 0] * w1b[(uu + 0) * HD];
                a1 += ss[uu + 1] * w1b[(uu + 1) * HD];
                a2 += ss[uu + 2] * w1b[(uu + 2) * HD];
                a3 += ss[uu + 3] * w1b[(uu + 3) * HD];
            }
            g_th[((size_t)n * HD + tid) * RD + rr] =
                __float2half_rn((a0 + a1) + (a2 + a3));
        }
    }
}

// ---------------------------------------------------------------------------
// Kernel B: v[tok,h] = relu( sum_r r[tok,rr] * t[n,rr,h] ) -> fp16, via
// mma.sync.m16n8k16.f16. Grid 128 = 64 token-tiles x 2 h-halves; 512 threads.
// ---------------------------------------------------------------------------
#define KB_SMEM ((128 * 132 + 64 * 132) * 4)

__global__ __launch_bounds__(512, 1) void kB(const float* __restrict__ r) {
    uint32_t* rsh = reinterpret_cast<uint32_t*>(g_smem_raw);           // [128][132]
    uint32_t* tsh = rsh + 128 * 132;                                   // [64][132]

    const int tid  = threadIdx.x;
    const int wid  = tid >> 5;
    const int lane = tid & 31;
    const int g    = lane >> 2;
    const int kl   = lane & 3;
    const int tile = blockIdx.x >> 1;
    const int hh   = blockIdx.x & 1;
    const int tok0 = tile * 128;
    const int hbase = hh * 64;
    const int n    = tok0 >> 10;
    const int tokgrp = wid >> 1;
    const int h32    = wid & 1;

    const float4* rg = reinterpret_cast<const float4*>(r + (size_t)tok0 * RD);
    #pragma unroll
    for (int j = 0; j < 16; j++) {
        int idx = tid + j * 512;
        int row = idx >> 6, c4 = idx & 63;
        float4 v = rg[idx];
        uint32_t p0, p1;
        PACK_H2(p0, v.x, v.y);
        PACK_H2(p1, v.z, v.w);
        *reinterpret_cast<uint2*>(&rsh[row * 132 + c4 * 2]) = make_uint2(p0, p1);
    }
    const uint32_t* tg = reinterpret_cast<const uint32_t*>(g_th)
                       + ((size_t)n * HD + hbase) * (RD / 2);
    #pragma unroll
    for (int j = 0; j < 16; j++) {
        int idx = tid + j * 512;
        int hl = idx >> 7, rr2 = idx & 127;
        tsh[hl * 132 + rr2] = tg[hl * (RD / 2) + rr2];
    }
    __syncthreads();

    float acc[4][4];
    #pragma unroll
    for (int nt = 0; nt < 4; nt++)
        #pragma unroll
        for (int q = 0; q < 4; q++) acc[nt][q] = 0.f;

    const int arow0 = (tokgrp * 16 + g) * 132;
    const int arow1 = (tokgrp * 16 + 8 + g) * 132;

    #pragma unroll
    for (int ks = 0; ks < 16; ks++) {
        uint32_t a0 = rsh[arow0 + ks * 8 + kl];
        uint32_t a1 = rsh[arow1 + ks * 8 + kl];
        uint32_t a2 = rsh[arow0 + ks * 8 + kl + 4];
        uint32_t a3 = rsh[arow1 + ks * 8 + kl + 4];
        #pragma unroll
        for (int nt = 0; nt < 4; nt++) {
            int hl = h32 * 32 + nt * 8 + g;
            uint32_t b0 = tsh[hl * 132 + ks * 8 + kl];
            uint32_t b1 = tsh[hl * 132 + ks * 8 + kl + 4];
            MMA_F16(acc[nt], a0, a1, a2, a3, b0, b1);
        }
    }

    uint32_t* vout = reinterpret_cast<uint32_t*>(g_vh);
    #pragma unroll
    for (int nt = 0; nt < 4; nt++) {
        int col32 = (hbase >> 1) + h32 * 16 + nt * 4 + kl;
        int row   = tok0 + tokgrp * 16 + g;
        uint32_t pl, ph;
        PACK_H2(pl, fmaxf(acc[nt][0], 0.f), fmaxf(acc[nt][1], 0.f));
        PACK_H2(ph, fmaxf(acc[nt][2], 0.f), fmaxf(acc[nt][3], 0.f));
        vout[(size_t)row * (HD / 2) + col32]       = pl;
        vout[(size_t)(row + 8) * (HD / 2) + col32] = ph;
    }
}

// ---------------------------------------------------------------------------
// Kernel C (dominant): out[t,vv] = sum_{x,h} (x[t,x]*v[t,h]) * w2[x,vv,h]
// NO block barriers in the mainloop: the 4 warps sharing a vv-quarter (one
// per SMSP) form a group with a private 3-slot smem ring (5KB slots, 320B
// vv-stride -> conflict-free LDS.128), group-local cp.async, and a named
// barrier (bar.sync vvq+1, 128). Warps on the same SMSP belong to different
// groups and drift freely. x tile fp16 (stride 136). Fused K-split combine.
// ---------------------------------------------------------------------------
#define SLOT_BYTES  5120                   // 16 vv x 320B (padded from 256)
#define SLOTS_BYTES (4 * 3 * SLOT_BYTES)   // 4 groups x 3 slots = 60KB
#define XS_H        136                    // x tile row stride in halves
#define KC_SMEM_DYN (SLOTS_BYTES + 128 * XS_H * 2)   // 60KB + 34KB = 94KB

__global__ __launch_bounds__(512, 1) void kC(const float* __restrict__ x,
                                             float* __restrict__ out) {
    __shared__ unsigned s_last;

    const int tid    = threadIdx.x;
    const int wid    = tid >> 5;
    const int lane   = tid & 31;
    const int g      = lane >> 2;
    const int kl     = lane & 3;
    const int split  = blockIdx.x >> 6;
    const int tile   = blockIdx.x & 63;
    const int tok0   = tile * 128;
    const int xbase  = split * 128;
    const int tokgrp = wid & 3;           // 0..3 : 32-token group (2 m16 tiles)
    const int vvq    = wid >> 2;          // 0..3 : 16-vv quarter (= warp group)

    char* grp_base = g_smem_raw + (size_t)vvq * 3 * SLOT_BYTES;
    uint32_t grp_sm;
    {
        uint64_t t0;
        asm("cvta.to.shared.u64 %0, %1;" : "=l"(t0) : "l"(grp_base));
        grp_sm = (uint32_t)t0;
    }

    // Group slice loader: 4KB (this group's 16 vv) for x0i -> slot x0i%3.
    // 128 group threads x 2 chunks of 16B, padded to 320B per vv.
    const int c0 = tokgrp * 64 + lane * 2;
    auto cpSlice = [&](int x0i) {
        uint32_t dst = grp_sm + (uint32_t)(x0i % 3) * SLOT_BYTES;
        const char* src = reinterpret_cast<const char*>(g_w2h)
                        + (size_t)(xbase + x0i) * 16384 + vvq * 4096;
        #pragma unroll
        for (int k = 0; k < 2; k++) {
            int c = c0 + k;
            uint32_t d = dst + (uint32_t)((c >> 4) * 320 + (c & 15) * 16);
            asm volatile("cp.async.cg.shared.global [%0], [%1], 16;"
                         :: "r"(d), "l"(src + c * 16) : "memory");
        }
        asm volatile("cp.async.commit_group;" ::: "memory");
    };

    cpSlice(0); cpSlice(1);

    // Stage x half-tile [128 tok x 128 x] as fp16, row stride 136 halves
    uint32_t* xu = reinterpret_cast<uint32_t*>(g_smem_raw + SLOTS_BYTES);
    {
        const float4* xg = reinterpret_cast<const float4*>(x + (size_t)tok0 * XD + xbase);
        #pragma unroll
        for (int j = 0; j < 8; j++) {
            int idx = tid + j * 512;           // 0..4095 float4
            int row = idx >> 5, c4 = idx & 31;
            float4 v = xg[row * (XD / 4) + c4];
            uint32_t p0, p1;
            PACK_H2(p0, v.x, v.y);
            PACK_H2(p1, v.z, v.w);
            *reinterpret_cast<uint2*>(&xu[row * (XS_H / 2) + c4 * 2]) = make_uint2(p0, p1);
        }
    }

    // v fragments (fp16-packed, all 128 h): 64 regs
    uint32_t vrl[2][2][8], vrh[2][2][8];
    #pragma unroll
    for (int mt = 0; mt < 2; mt++)
        #pragma unroll
        for (int rr2 = 0; rr2 < 2; rr2++) {
            int row = tok0 + tokgrp * 32 + mt * 16 + rr2 * 8 + g;
            const uint32_t* vp = reinterpret_cast<const uint32_t*>(g_vh + (size_t)row * HD);
            #pragma unroll
            for (int ch = 0; ch < 8; ch++) {
                vrl[mt][rr2][ch] = vp[ch * 8 + kl];
                vrh[mt][rr2][ch] = vp[ch * 8 + kl + 4];
            }
        }
    __syncthreads();   // x tile ready (only block-wide barrier before combine)

    float acc[2][2][4];
    #pragma unroll
    for (int mt = 0; mt < 2; mt++)
        #pragma unroll
        for (int nt = 0; nt < 2; nt++)
            #pragma unroll
            for (int q = 0; q < 4; q++) acc[mt][nt][q] = 0.f;

    const unsigned short* xsh = reinterpret_cast<const unsigned short*>(xu);
    const int r00 = (tokgrp * 32 +      g) * XS_H;
    const int r01 = (tokgrp * 32 +  8 + g) * XS_H;
    const int r10 = (tokgrp * 32 + 16 + g) * XS_H;
    const int r11 = (tokgrp * 32 + 24 + g) * XS_H;
    const int bar_id = vvq + 1;

    for (int x0 = 0; x0 < 128; x0++) {
        asm volatile("cp.async.wait_group 1;" ::: "memory");
        asm volatile("bar.sync %0, 128;" :: "r"(bar_id) : "memory");
        if (x0 + 2 < 128) cpSlice(x0 + 2);
        else asm volatile("cp.async.commit_group;" ::: "memory");  // keep accounting

        const char* slp = grp_base + (x0 % 3) * SLOT_BYTES;
        uint32_t xp00, xp01, xp10, xp11;
        SPLAT16(xp00, xsh[r00 + x0]);
        SPLAT16(xp01, xsh[r01 + x0]);
        SPLAT16(xp10, xsh[r10 + x0]);
        SPLAT16(xp11, xsh[r11 + x0]);

        #pragma unroll
        for (int hcp = 0; hcp < 4; hcp++) {
            uint32_t A[2][2][4];
            #pragma unroll
            for (int cc = 0; cc < 2; cc++) {
                int ch = hcp * 2 + cc;
                HMUL2(A[cc][0][0], xp00, vrl[0][0][ch]);
                HMUL2(A[cc][0][1], xp01, vrl[0][1][ch]);
                HMUL2(A[cc][0][2], xp00, vrh[0][0][ch]);
                HMUL2(A[cc][0][3], xp01, vrh[0][1][ch]);
                HMUL2(A[cc][1][0], xp10, vrl[1][0][ch]);
                HMUL2(A[cc][1][1], xp11, vrl[1][1][ch]);
                HMUL2(A[cc][1][2], xp10, vrh[1][0][ch]);
                HMUL2(A[cc][1][3], xp11, vrh[1][1][ch]);
            }
            #pragma unroll
            for (int nt = 0; nt < 2; nt++) {
                uint4 Bv = *reinterpret_cast<const uint4*>(
                    slp + (nt * 8 + g) * 320 + hcp * 64 + kl * 16);
                MMA_F16(acc[0][nt], A[0][0][0], A[0][0][1], A[0][0][2], A[0][0][3], Bv.x, Bv.y);
                MMA_F16(acc[1][nt], A[0][1][0], A[0][1][1], A[0][1][2], A[0][1][3], Bv.x, Bv.y);
                MMA_F16(acc[0][nt], A[1][0][0], A[1][0][1], A[1][0][2], A[1][0][3], Bv.z, Bv.w);
                MMA_F16(acc[1][nt], A[1][1][0], A[1][1][1], A[1][1][2], A[1][1][3], Bv.z, Bv.w);
            }
        }
    }

    // Write own partials (scaled by 1024)
    float* pp = g_part[split];
    #pragma unroll
    for (int mt = 0; mt < 2; mt++) {
        int r0 = tok0 + tokgrp * 32 + mt * 16 + g;
        #pragma unroll
        for (int nt = 0; nt < 2; nt++) {
            int col = vvq * 16 + nt * 8 + kl * 2;
            *reinterpret_cast<float2*>(&pp[(size_t)r0 * VD + col]) =
                make_float2(acc[mt][nt][0], acc[mt][nt][1]);
            *reinterpret_cast<float2*>(&pp[(size_t)(r0 + 8) * VD + col]) =
                make_float2(acc[mt][nt][2], acc[mt][nt][3]);
        }
    }

    // Fused combine: last split per tile sums and writes out
    __threadfence();
    __syncthreads();
    if (tid == 0) s_last = atomicAdd(&g_cnt[tile], 1);
    __syncthreads();
    if (s_last == 1) {
        __threadfence();
        const float S = 1.0f / 1024.0f;
        const float* peer = g_part[1 - split];
        #pragma unroll
        for (int mt = 0; mt < 2; mt++) {
            int r0 = tok0 + tokgrp * 32 + mt * 16 + g;
            #pragma unroll
            for (int nt = 0; nt < 2; nt++) {
                int col = vvq * 16 + nt * 8 + kl * 2;
                float2 q0 = *reinterpret_cast<const float2*>(&peer[(size_t)r0 * VD + col]);
                float2 q1 = *reinterpret_cast<const float2*>(&peer[(size_t)(r0 + 8) * VD + col]);
                *reinterpret_cast<float2*>(&out[(size_t)r0 * VD + col]) =
                    make_float2((acc[mt][nt][0] + q0.x) * S, (acc[mt][nt][1] + q0.y) * S);
                *reinterpret_cast<float2*>(&out[(size_t)(r0 + 8) * VD + col]) =
                    make_float2((acc[mt][nt][2] + q1.x) * S, (acc[mt][nt][3] + q1.y) * S);
            }
        }
        if (tid == 0) g_cnt[tile] = 0;   // self-reset for next launch/replay
    }
}

// ---------------------------------------------------------------------------
extern "C" void kernel_launch(void* const* d_in, const int* in_sizes, int n_in,
                              void* d_out, int out_size) {
    const float* x  = (const float*)d_in[0];
    const float* r  = (const float*)d_in[1];
    const float* u  = (const float*)d_in[2];
    const float* w1 = (const float*)d_in[3];
    const float* w2 = (const float*)d_in[4];
    float* out = (float*)d_out;

    cudaFuncSetAttribute(kC, cudaFuncAttributeMaxDynamicSharedMemorySize, KC_SMEM_DYN);
    cudaFuncSetAttribute(kB, cudaFuncAttributeMaxDynamicSharedMemorySize, KB_SMEM);

    kW<<<(XD * VD * HD) / (256 * 8), 256>>>(w2);   // 1024 blocks — 8 halves/thread
    kA<<<RD, 256>>>(u, w1);
    kB<<<NTOK / 64, 512, KB_SMEM>>>(r);
    kC<<<128, 512, KC_SMEM_DYN>>>(x, out);
}